// round 2
// baseline (speedup 1.0000x reference)
#include <cuda_runtime.h>
#include <cstdint>

typedef unsigned long long ull;

#define QL    2048
#define HISTL 2048
#define KLEN  4096
#define NH    12
#define NKVH  2
#define HD    128
#define HID   1536
#define GRP   6

// ---------------- scratch (static device globals; no allocation) ----------------
__device__ float g_q[QL * HID];          // Q projection, then RoPE'd in place: [t][h*128+d]
__device__ float g_kn[QL * NKVH * HD];   // new K projection (pre-RoPE)
__device__ float g_vn[QL * NKVH * HD];   // new V projection
__device__ float g_k[NKVH * KLEN * HD];  // full K: [kvh][pos][d]
__device__ float g_v[NKVH * KLEN * HD];  // full V
__device__ float g_attn[QL * HID];       // attention output pre-Wo

// ---------------- f32x2 packed helpers (Blackwell FFMA2) ----------------
__device__ __forceinline__ ull pack2(float lo, float hi) {
    ull r; asm("mov.b64 %0, {%1, %2};" : "=l"(r) : "f"(lo), "f"(hi)); return r;
}
__device__ __forceinline__ float2 unpack2(ull v) {
    float2 f; asm("mov.b64 {%0, %1}, %2;" : "=f"(f.x), "=f"(f.y) : "l"(v)); return f;
}
__device__ __forceinline__ ull fma2(ull a, ull b, ull c) {
    ull d; asm("fma.rn.f32x2 %0, %1, %2, %3;" : "=l"(d) : "l"(a), "l"(b), "l"(c)); return d;
}
__device__ __forceinline__ ull mul2(ull a, ull b) {
    ull d; asm("mul.rn.f32x2 %0, %1, %2;" : "=l"(d) : "l"(a), "l"(b)); return d;
}

// ---------------- 128x128x8 SGEMM tile (f32x2 inner product) ----------------
// C[m0..m0+127][0..127 local] = A[m0..][:K] * B[:K][0..127 local] (+bias)
// A row-major lda, B row-major ldb (already offset to its column base),
// C already offset to its column base, row stride ldc.
__device__ __forceinline__ void gemm_tile_128(
    const float* __restrict__ A, int lda,
    const float* __restrict__ B, int ldb,
    const float* __restrict__ bias,      // local col index, may be null
    float* __restrict__ C, int ldc,
    int m0, int K,
    ull* As2, float* Bs)
{
    const int tid = threadIdx.x;
    const int ty = tid >> 4, tx = tid & 15;

    ull acc[8][4];
#pragma unroll
    for (int i = 0; i < 8; i++)
#pragma unroll
        for (int c = 0; c < 4; c++) acc[i][c] = 0ull;

    const int ar = tid >> 1;             // tile row this thread loads (0..127)
    const int ak = (tid & 1) * 4;        // k sub-offset 0 or 4
    const float* Aptr = A + (ull)(m0 + ar) * lda + ak;
    const int bk = tid >> 5;             // 0..7
    const int bc = (tid & 31) * 4;       // 0..124
    const float* Bptr = B + (ull)bk * ldb + bc;

    for (int k0 = 0; k0 < K; k0 += 8) {
        float4 av = *(const float4*)(Aptr + k0);
        float4 bv = *(const float4*)(Bptr + (ull)k0 * ldb);
        __syncthreads();
        As2[(ak + 0) * 128 + ar] = pack2(av.x, av.x);
        As2[(ak + 1) * 128 + ar] = pack2(av.y, av.y);
        As2[(ak + 2) * 128 + ar] = pack2(av.z, av.z);
        As2[(ak + 3) * 128 + ar] = pack2(av.w, av.w);
        *(float4*)(Bs + bk * 128 + bc) = bv;
        __syncthreads();
#pragma unroll
        for (int kk = 0; kk < 8; kk++) {
            ull a2[8], b2[4];
            const ull* ap = As2 + kk * 128 + ty * 8;
#pragma unroll
            for (int i = 0; i < 8; i++) a2[i] = ap[i];
            const ull* bp = (const ull*)(Bs + kk * 128);
#pragma unroll
            for (int c = 0; c < 4; c++) b2[c] = bp[tx + c * 16];
#pragma unroll
            for (int i = 0; i < 8; i++)
#pragma unroll
                for (int c = 0; c < 4; c++) acc[i][c] = fma2(a2[i], b2[c], acc[i][c]);
        }
    }

#pragma unroll
    for (int i = 0; i < 8; i++) {
        const int row = m0 + ty * 8 + i;
        float* crow = C + (ull)row * ldc;
#pragma unroll
        for (int c = 0; c < 4; c++) {
            const int col = 2 * (tx + c * 16);
            float2 v = unpack2(acc[i][c]);
            if (bias) { v.x += bias[col]; v.y += bias[col + 1]; }
            crow[col] = v.x;
            crow[col + 1] = v.y;
        }
    }
}

// ---------------- fused QKV projection ----------------
// grid (16, 16): blockIdx.x = output 128-col block over [Wq | Wk | Wv] (12 + 2 + 2)
__global__ __launch_bounds__(256, 2) void qkv_gemm_kernel(
    const float* __restrict__ x,
    const float* __restrict__ Wq, const float* __restrict__ bq,
    const float* __restrict__ Wk, const float* __restrict__ bk,
    const float* __restrict__ Wv, const float* __restrict__ bv)
{
    __shared__ ull As2[8 * 128];
    __shared__ float Bs[8 * 128];
    const int nb = blockIdx.x;
    const int m0 = blockIdx.y * 128;

    const float *B, *bias;
    float* C;
    int ldb, ldc;
    if (nb < 12)      { B = Wq + nb * 128;        bias = bq + nb * 128;        C = g_q  + nb * 128;        ldb = HID;       ldc = HID; }
    else if (nb < 14) { B = Wk + (nb - 12) * 128; bias = bk + (nb - 12) * 128; C = g_kn + (nb - 12) * 128; ldb = NKVH * HD; ldc = NKVH * HD; }
    else              { B = Wv + (nb - 14) * 128; bias = bv + (nb - 14) * 128; C = g_vn + (nb - 14) * 128; ldb = NKVH * HD; ldc = NKVH * HD; }

    gemm_tile_128(x, HID, B, ldb, bias, C, ldc, m0, HID, As2, Bs);
}

// ---------------- output projection ----------------
__global__ __launch_bounds__(256, 2) void out_gemm_kernel(
    const float* __restrict__ Wo, float* __restrict__ out)
{
    __shared__ ull As2[8 * 128];
    __shared__ float Bs[8 * 128];
    const int nb = blockIdx.x;      // 0..11
    const int m0 = blockIdx.y * 128;
    gemm_tile_128(g_attn, HID, Wo + nb * 128, HID, (const float*)0,
                  out + nb * 128, HID, m0, HID, As2, Bs);
}

// ---------------- RoPE on Q (in place) ----------------
// grid(QL), block(NH*64 = 768)
__global__ void rope_q_kernel(const float* __restrict__ fcos, const float* __restrict__ fsin)
{
    const int t = blockIdx.x;
    const int h = threadIdx.x >> 6;     // 0..11
    const int i = threadIdx.x & 63;     // 0..63
    float* q = g_q + (ull)t * HID + h * HD;
    const float c = fcos[t * 64 + i];
    const float s = fsin[t * 64 + i];
    const float x1 = q[i];
    const float x2 = q[i + 64];
    q[i]      = x1 * c - x2 * s;
    q[i + 64] = x1 * s + x2 * c;
}

// ---------------- build full K/V (history + RoPE'd new K, plain new V) ----------------
// grid(KLEN, NKVH), block(64)
__global__ void build_kv_kernel(
    const float* __restrict__ k_hist, const float* __restrict__ v_hist,
    const float* __restrict__ fcos, const float* __restrict__ fsin)
{
    const int pos = blockIdx.x;
    const int kv = blockIdx.y;
    const int i = threadIdx.x;   // 0..63
    float* kd = g_k + ((ull)(kv * KLEN + pos)) * HD;
    float* vd = g_v + ((ull)(kv * KLEN + pos)) * HD;
    if (pos < HISTL) {
        const float* ks = k_hist + ((ull)pos * NKVH + kv) * HD;
        const float* vs = v_hist + ((ull)pos * NKVH + kv) * HD;
        kd[i] = ks[i]; kd[i + 64] = ks[i + 64];
        vd[i] = vs[i]; vd[i + 64] = vs[i + 64];
    } else {
        const int t = pos - HISTL;
        const float* ks = g_kn + (ull)t * (NKVH * HD) + kv * HD;
        const float* vs = g_vn + (ull)t * (NKVH * HD) + kv * HD;
        const float c = fcos[t * 64 + i];
        const float s = fsin[t * 64 + i];
        const float x1 = ks[i];
        const float x2 = ks[i + 64];
        kd[i]      = x1 * c - x2 * s;
        kd[i + 64] = x1 * s + x2 * c;
        vd[i] = vs[i]; vd[i + 64] = vs[i + 64];
    }
}

// ---------------- flash attention ----------------
// grid(NH, 32), 256 threads. 64-query x 64-key tiles, online softmax.
// SMEM: Qs[64][130] Ks[64][130] Vs[64][130] Ps[64][65]  => 116480 bytes (dynamic)
#define ASTR 130
#define ATT_SMEM ((3 * 64 * ASTR + 64 * 65) * 4)

__global__ __launch_bounds__(256) void attention_kernel()
{
    extern __shared__ float sm[];
    float* Qs = sm;
    float* Ks = Qs + 64 * ASTR;
    float* Vs = Ks + 64 * ASTR;
    float* Ps = Vs + 64 * ASTR;

    const int h = blockIdx.x;
    const int qb = 31 - blockIdx.y;       // heavy blocks first
    const int kvh = h / GRP;
    const int tid = threadIdx.x;
    const int ty = tid >> 4, tx = tid & 15;
    const int q0 = qb * 64;

    // load Q tile (64 x 128)
#pragma unroll
    for (int it = 0; it < 8; it++) {
        const int idx = tid + it * 256;
        const int r = idx >> 5, c4 = (idx & 31) * 4;
        float4 v = *(const float4*)(g_q + (ull)(q0 + r) * HID + h * HD + c4);
        float* d = Qs + r * ASTR + c4;
        d[0] = v.x; d[1] = v.y; d[2] = v.z; d[3] = v.w;
    }

    float m[4], l[4];
    ull acc[4][4];
#pragma unroll
    for (int i = 0; i < 4; i++) {
        m[i] = -1e30f; l[i] = 0.f;
#pragma unroll
        for (int c = 0; c < 4; c++) acc[i][c] = 0ull;
    }

    const int n_tiles = qb + 33;
    const float* kbaseptr = g_k + (ull)kvh * KLEN * HD;
    const float* vbaseptr = g_v + (ull)kvh * KLEN * HD;

    for (int kt = 0; kt < n_tiles; kt++) {
        const int kb = kt * 64;
        __syncthreads();
        // load K,V tile (64 x 128 each)
#pragma unroll
        for (int it = 0; it < 8; it++) {
            const int idx = tid + it * 256;
            const int r = idx >> 5, c4 = (idx & 31) * 4;
            float4 kv4 = *(const float4*)(kbaseptr + (ull)(kb + r) * HD + c4);
            float* kd = Ks + r * ASTR + c4;
            kd[0] = kv4.x; kd[1] = kv4.y; kd[2] = kv4.z; kd[3] = kv4.w;
            float4 vv4 = *(const float4*)(vbaseptr + (ull)(kb + r) * HD + c4);
            float* vdp = Vs + r * ASTR + c4;
            vdp[0] = vv4.x; vdp[1] = vv4.y; vdp[2] = vv4.z; vdp[3] = vv4.w;
        }
        __syncthreads();

        // S = Q K^T  (f32x2 packed over contraction dim)
        ull s2[4][4];
#pragma unroll
        for (int i = 0; i < 4; i++)
#pragma unroll
            for (int j = 0; j < 4; j++) s2[i][j] = 0ull;

#pragma unroll 2
        for (int kp = 0; kp < 64; kp++) {
            ull q2[4], k2[4];
#pragma unroll
            for (int i = 0; i < 4; i++)
                q2[i] = *(const ull*)(Qs + (ty * 4 + i) * ASTR + 2 * kp);
#pragma unroll
            for (int j = 0; j < 4; j++)
                k2[j] = *(const ull*)(Ks + (tx + j * 16) * ASTR + 2 * kp);
#pragma unroll
            for (int i = 0; i < 4; i++)
#pragma unroll
                for (int j = 0; j < 4; j++) s2[i][j] = fma2(q2[i], k2[j], s2[i][j]);
        }

        const bool maskt = (kt == qb + 32);
#pragma unroll
        for (int i = 0; i < 4; i++) {
            const int qg = q0 + ty * 4 + i;
            float sv[4];
#pragma unroll
            for (int j = 0; j < 4; j++) {
                float2 t2 = unpack2(s2[i][j]);
                float s = (t2.x + t2.y) * 0.08838834764831845f;
                if (maskt) {
                    const int kg = kb + tx + j * 16;
                    if (kg > qg + HISTL) s = -1e30f;
                }
                sv[j] = s;
            }
            float rmax = fmaxf(fmaxf(sv[0], sv[1]), fmaxf(sv[2], sv[3]));
#pragma unroll
            for (int off = 8; off >= 1; off >>= 1)
                rmax = fmaxf(rmax, __shfl_xor_sync(0xffffffffu, rmax, off, 16));
            const float mnew = fmaxf(m[i], rmax);
            const float corr = __expf(m[i] - mnew);
            float rsum = 0.f;
            float p[4];
#pragma unroll
            for (int j = 0; j < 4; j++) { p[j] = __expf(sv[j] - mnew); rsum += p[j]; }
#pragma unroll
            for (int off = 8; off >= 1; off >>= 1)
                rsum += __shfl_xor_sync(0xffffffffu, rsum, off, 16);
            l[i] = l[i] * corr + rsum;
            m[i] = mnew;
            const ull c2 = pack2(corr, corr);
#pragma unroll
            for (int c = 0; c < 4; c++) acc[i][c] = mul2(acc[i][c], c2);
#pragma unroll
            for (int j = 0; j < 4; j++)
                Ps[(ty * 4 + i) * 65 + tx + j * 16] = p[j];
        }
        __syncthreads();

        // acc += P @ V  (f32x2 packed over output columns)
#pragma unroll 2
        for (int j = 0; j < 64; j++) {
            ull v2[4];
#pragma unroll
            for (int c = 0; c < 4; c++)
                v2[c] = *(const ull*)(Vs + j * ASTR + 2 * (tx + c * 16));
#pragma unroll
            for (int i = 0; i < 4; i++) {
                const float pv = Ps[(ty * 4 + i) * 65 + j];
                const ull p2 = pack2(pv, pv);
#pragma unroll
                for (int c = 0; c < 4; c++) acc[i][c] = fma2(p2, v2[c], acc[i][c]);
            }
        }
    }

    // epilogue: normalize, write to g_attn [t][h*128+d]
#pragma unroll
    for (int i = 0; i < 4; i++) {
        const float inv = 1.f / l[i];
        const int row = q0 + ty * 4 + i;
        float* dst = g_attn + (ull)row * HID + h * HD;
#pragma unroll
        for (int c = 0; c < 4; c++) {
            float2 v = unpack2(acc[i][c]);
            const int col = 2 * (tx + c * 16);
            dst[col] = v.x * inv;
            dst[col + 1] = v.y * inv;
        }
    }
}

// ---------------- launch ----------------
extern "C" void kernel_launch(void* const* d_in, const int* in_sizes, int n_in,
                              void* d_out, int out_size)
{
    const float* x     = (const float*)d_in[0];
    const float* Wq    = (const float*)d_in[1];
    const float* bq    = (const float*)d_in[2];
    const float* Wk    = (const float*)d_in[3];
    const float* bk    = (const float*)d_in[4];
    const float* Wv    = (const float*)d_in[5];
    const float* bv    = (const float*)d_in[6];
    const float* Wo    = (const float*)d_in[7];
    const float* khist = (const float*)d_in[8];
    const float* vhist = (const float*)d_in[9];
    const float* fcos  = (const float*)d_in[10];
    const float* fsin  = (const float*)d_in[11];
    float* out = (float*)d_out;

    cudaFuncSetAttribute(attention_kernel,
                         cudaFuncAttributeMaxDynamicSharedMemorySize, ATT_SMEM);

    qkv_gemm_kernel<<<dim3(16, 16), 256>>>(x, Wq, bq, Wk, bk, Wv, bv);
    rope_q_kernel<<<QL, NH * 64>>>(fcos, fsin);
    build_kv_kernel<<<dim3(KLEN, NKVH), 64>>>(khist, vhist, fcos, fsin);
    attention_kernel<<<dim3(NH, 32), 256, ATT_SMEM>>>();
    out_gemm_kernel<<<dim3(12, 16), 256>>>(Wo, out);
}